// round 1
// baseline (speedup 1.0000x reference)
#include <cuda_runtime.h>
#include <cstdint>

// Problem constants
#define NSAMPLES   524288
#define NFEAT      64
#define NGATES     64
#define NOUT       8
#define BASEN      66            // NFEAT + 2 (const-0 and const-1 entries)
#define MAXCONN    130           // BASEN + NGATES
#define BLK        128
#define STRIDE     129           // BLK + 1 (odd -> bank-conflict-free columns)
#define SMEM_BYTES (MAXCONN * STRIDE * 4)

// Gate wiring computed on device, then mirrored into constant memory.
__device__   uint2 g_off[NGATES];        // byte offsets of (a, b) operands into smem column
__constant__ uint2 c_off[NGATES];
__constant__ float c_w[NGATES * NOUT];   // output_weights
__constant__ float c_scale[NOUT];        // output_scale

// ---------------------------------------------------------------------------
// Prep: top-2 of gate_weights[i, 0 : 66+i].  Softmax is monotonic, so top-2 of
// the softmax probs == top-2 of the raw (masked) logits.  Strict '>' comparison
// reproduces top_k's lower-index-wins tie-breaking.
// ---------------------------------------------------------------------------
__global__ void prep_kernel(const float* __restrict__ gw) {
    int i = threadIdx.x;              // one thread per gate, 64 threads
    const float* row = gw + i * MAXCONN;
    int n = BASEN + i;
    float v1 = -3.4e38f, v2 = -3.4e38f;
    int i1 = 0, i2 = 0;
    for (int j = 0; j < n; ++j) {
        float v = row[j];
        if (v > v1)      { v2 = v1; i2 = i1; v1 = v; i1 = j; }
        else if (v > v2) { v2 = v;  i2 = j; }
    }
    g_off[i] = make_uint2((unsigned)(i1 * STRIDE * 4),
                          (unsigned)(i2 * STRIDE * 4));
}

// ---------------------------------------------------------------------------
// Main: one thread = one sample.  Per-sample buffer lives in smem laid out
// [entry][sample] with STRIDE=129 -> every warp access (uniform entry index,
// consecutive samples) is one conflict-free 128B wavefront.
// Output accumulation (64x8 matvec) is fused into the gate loop; weights come
// from constant memory with compile-time offsets (full unroll) so they stay
// off the smem port.
// ---------------------------------------------------------------------------
__global__ void __launch_bounds__(BLK)
circuit_kernel(const float* __restrict__ X, float* __restrict__ out) {
    extern __shared__ float sbuf[];
    const int tid = threadIdx.x;
    const long long base = (long long)blockIdx.x * BLK;

    // Load X tile transposed into smem.
    // i = k*128 + tid is globally coalesced; f = i&63, s = i>>6 gives
    // bank (f*129 + s) % 32 = (f + s) % 32 -> conflict-free STS.
    const float* Xb = X + base * NFEAT;
#pragma unroll
    for (int k = 0; k < NFEAT; ++k) {
        int i = k * BLK + tid;
        int s = i >> 6;
        int f = i & 63;
        sbuf[f * STRIDE + s] = Xb[i];
    }
    // Constant entries: buf[64] = 0, buf[65] = 1
    sbuf[64 * STRIDE + tid] = 0.0f;
    sbuf[65 * STRIDE + tid] = 1.0f;
    __syncthreads();

    char* col = (char*)(sbuf + tid);   // this thread's sample column (byte base)
    float acc[NOUT];
#pragma unroll
    for (int j = 0; j < NOUT; ++j) acc[j] = 0.0f;

#pragma unroll
    for (int i = 0; i < NGATES; ++i) {
        uint2 o = c_off[i];                        // uniform constant load
        float a = *(const float*)(col + o.x);      // LDS, 1 wavefront
        float b = *(const float*)(col + o.y);      // LDS, 1 wavefront
        float g = fmaf(-a, b, 1.0f);               // g = 1 - a*b
        *(float*)(col + (unsigned)((BASEN + i) * STRIDE * 4)) = g;  // STS, imm offset
#pragma unroll
        for (int j = 0; j < NOUT; ++j)
            acc[j] = fmaf(g, c_w[i * NOUT + j], acc[j]);
    }

    float4 r0 = make_float4(acc[0] * c_scale[0], acc[1] * c_scale[1],
                            acc[2] * c_scale[2], acc[3] * c_scale[3]);
    float4 r1 = make_float4(acc[4] * c_scale[4], acc[5] * c_scale[5],
                            acc[6] * c_scale[6], acc[7] * c_scale[7]);
    float4* op = (float4*)(out + (base + tid) * NOUT);
    op[0] = r0;                                    // 2x STG.128, coalesced
    op[1] = r1;
}

// ---------------------------------------------------------------------------
// Launch: prep -> mirror wiring/weights into constant bank -> main kernel.
// All ops are graph-capturable (kernels + async D2D memcpys only).
// ---------------------------------------------------------------------------
extern "C" void kernel_launch(void* const* d_in, const int* in_sizes, int n_in,
                              void* d_out, int out_size) {
    const float* X  = (const float*)d_in[0];  // (524288, 64)
    const float* gw = (const float*)d_in[1];  // (64, 130)
    const float* ow = (const float*)d_in[2];  // (64, 8)
    const float* sc = (const float*)d_in[3];  // (8,)
    float* out = (float*)d_out;               // (524288, 8)

    cudaFuncSetAttribute((const void*)circuit_kernel,
                         cudaFuncAttributeMaxDynamicSharedMemorySize, SMEM_BYTES);

    prep_kernel<<<1, 64>>>(gw);

    void* gp = nullptr;
    cudaGetSymbolAddress(&gp, g_off);
    cudaMemcpyToSymbolAsync(c_off, gp, sizeof(uint2) * NGATES, 0,
                            cudaMemcpyDeviceToDevice, 0);
    cudaMemcpyToSymbolAsync(c_w, ow, sizeof(float) * NGATES * NOUT, 0,
                            cudaMemcpyDeviceToDevice, 0);
    cudaMemcpyToSymbolAsync(c_scale, sc, sizeof(float) * NOUT, 0,
                            cudaMemcpyDeviceToDevice, 0);

    circuit_kernel<<<NSAMPLES / BLK, BLK, SMEM_BYTES>>>(X, out);
}

// round 2
// speedup vs baseline: 1.2026x; 1.2026x over previous
#include <cuda_runtime.h>
#include <cstdint>

// Problem constants
#define NSAMPLES   524288
#define NFEAT      64
#define NGATES     64
#define NOUT       8
#define BASEN      66            // NFEAT + 2 (const-0 and const-1 entries)
#define MAXCONN    130           // BASEN + NGATES
#define BLK        128
#define STRIDE     129           // BLK + 1 (conflict-free transpose store)
#define SMEM_BYTES (MAXCONN * STRIDE * 4)

// All per-launch parameters in ONE constant block (single memcpy node).
struct Params {
    uint2 off[NGATES];               // byte offsets of (a, b) operands
    float w[NGATES][NOUT];           // output_weights * output_scale (pre-folded)
};
__device__   Params g_stage;
__constant__ Params c_p;

// ---------------------------------------------------------------------------
// Prep: top-2 of gate_weights[i, 0 : 66+i]. Softmax is monotonic, so top-2 of
// probs == top-2 of raw logits; strict '>' reproduces top_k tie-breaking.
// Also folds output_scale into the weights.
// ---------------------------------------------------------------------------
__global__ void prep_kernel(const float* __restrict__ gw,
                            const float* __restrict__ ow,
                            const float* __restrict__ sc) {
    int i = threadIdx.x;              // one thread per gate, 64 threads
    const float* row = gw + i * MAXCONN;
    int n = BASEN + i;
    float v1 = -3.4e38f, v2 = -3.4e38f;
    int i1 = 0, i2 = 0;
    for (int j = 0; j < n; ++j) {
        float v = row[j];
        if (v > v1)      { v2 = v1; i2 = i1; v1 = v; i1 = j; }
        else if (v > v2) { v2 = v;  i2 = j; }
    }
    g_stage.off[i] = make_uint2((unsigned)(i1 * STRIDE * 4),
                                (unsigned)(i2 * STRIDE * 4));
#pragma unroll
    for (int j = 0; j < NOUT; ++j)
        g_stage.w[i][j] = ow[i * NOUT + j] * sc[j];
}

// ---------------------------------------------------------------------------
// Main: one thread = one sample; per-sample buffer in smem [entry][sample].
// Gate loop is software-pipelined depth 2: operands for gate i+2 are loaded
// BEFORE gate i's STS. A prefetched operand is stale only if its offset equals
// slot(i) or slot(i+1) — compile-time constants after full unroll — fixed up
// with a predicated move of the in-register gate value.
// ---------------------------------------------------------------------------
__global__ void __launch_bounds__(BLK)
circuit_kernel(const float* __restrict__ X, float* __restrict__ out) {
    extern __shared__ float sbuf[];
    const int tid = threadIdx.x;
    const long long base = (long long)blockIdx.x * BLK;

    // Load X tile transposed into smem via float4 streaming loads.
    // float4 index k*BLK+tid covers elements e=4*(k*BLK+tid)..+3:
    // sample s = e>>6, feature f = e&63; bank (f*129+s)%32 = (f+s)%32 -> CF.
    const float4* Xb = (const float4*)(X + base * NFEAT);
#pragma unroll
    for (int k = 0; k < NFEAT / 4; ++k) {
        float4 v = __ldcs(&Xb[k * BLK + tid]);
        int e = 4 * (k * BLK + tid);
        int s = e >> 6;
        int f = e & 63;
        sbuf[(f + 0) * STRIDE + s] = v.x;
        sbuf[(f + 1) * STRIDE + s] = v.y;
        sbuf[(f + 2) * STRIDE + s] = v.z;
        sbuf[(f + 3) * STRIDE + s] = v.w;
    }
    sbuf[64 * STRIDE + tid] = 0.0f;   // const 0
    sbuf[65 * STRIDE + tid] = 1.0f;   // const 1
    __syncthreads();

    char* col = (char*)(sbuf + tid);  // this sample's column (byte base)
    float acc[NOUT];
#pragma unroll
    for (int j = 0; j < NOUT; ++j) acc[j] = 0.0f;

    float A[NGATES], B[NGATES];       // short live ranges -> registers
    // Initial prefetch. Gate 0 operands always point into the X/const region.
    // Gate 1 may reference slot(0); fixed up at i=0.
    {
        uint2 o0 = c_p.off[0], o1 = c_p.off[1];
        A[0] = *(const float*)(col + o0.x);
        B[0] = *(const float*)(col + o0.y);
        A[1] = *(const float*)(col + o1.x);
        B[1] = *(const float*)(col + o1.y);
    }

#pragma unroll
    for (int i = 0; i < NGATES; ++i) {
        float g = fmaf(-A[i], B[i], 1.0f);           // g = 1 - a*b

        uint2 onx;                                    // prefetch i+2 (pre-STS)
        if (i + 2 < NGATES) {
            onx = c_p.off[i + 2];
            A[i + 2] = *(const float*)(col + onx.x);
            B[i + 2] = *(const float*)(col + onx.y);
        }

        const unsigned Si = (unsigned)((BASEN + i) * STRIDE * 4);
        *(float*)(col + Si) = g;                      // STS, immediate offset

#pragma unroll
        for (int j = 0; j < NOUT; ++j)
            acc[j] = fmaf(g, c_p.w[i][j], acc[j]);

        // Fixups: pending prefetched operands stale w.r.t. slot(i).
        if (i + 1 < NGATES) {
            uint2 o1 = c_p.off[i + 1];
            if (o1.x == Si) A[i + 1] = g;
            if (o1.y == Si) B[i + 1] = g;
        }
        if (i + 2 < NGATES) {
            if (onx.x == Si) A[i + 2] = g;
            if (onx.y == Si) B[i + 2] = g;
        }
    }

    float4 r0 = make_float4(acc[0], acc[1], acc[2], acc[3]);
    float4 r1 = make_float4(acc[4], acc[5], acc[6], acc[7]);
    float4* op = (float4*)(out + (base + tid) * NOUT);
    __stcs(&op[0], r0);                               // streaming STG.128
    __stcs(&op[1], r1);
}

// ---------------------------------------------------------------------------
// Launch: prep -> ONE memcpy into the constant bank -> main kernel (3 nodes).
// ---------------------------------------------------------------------------
extern "C" void kernel_launch(void* const* d_in, const int* in_sizes, int n_in,
                              void* d_out, int out_size) {
    const float* X  = (const float*)d_in[0];  // (524288, 64)
    const float* gw = (const float*)d_in[1];  // (64, 130)
    const float* ow = (const float*)d_in[2];  // (64, 8)
    const float* sc = (const float*)d_in[3];  // (8,)
    float* out = (float*)d_out;               // (524288, 8)

    cudaFuncSetAttribute((const void*)circuit_kernel,
                         cudaFuncAttributeMaxDynamicSharedMemorySize, SMEM_BYTES);

    prep_kernel<<<1, 64>>>(gw, ow, sc);

    void* gp = nullptr;
    cudaGetSymbolAddress(&gp, g_stage);
    cudaMemcpyToSymbolAsync(c_p, gp, sizeof(Params), 0,
                            cudaMemcpyDeviceToDevice, 0);

    circuit_kernel<<<NSAMPLES / BLK, BLK, SMEM_BYTES>>>(X, out);
}

// round 3
// speedup vs baseline: 1.2766x; 1.0616x over previous
#include <cuda_runtime.h>
#include <cstdint>

// Problem constants
#define NSAMPLES   524288
#define NFEAT      64
#define NGATES     64
#define NOUT       8
#define BASEN      66            // NFEAT + 2 (const-0 and const-1 entries)
#define MAXCONN    130           // BASEN + NGATES
#define BLK        128
#define STRIDE     129           // BLK + 1 (conflict-free transpose store)
#define SMEM_BYTES (MAXCONN * STRIDE * 4)

// All per-launch parameters in ONE constant block (single memcpy node).
struct Params {
    uint2 off[NGATES];               // byte offsets of (a, b) operands
    float w[NGATES][NOUT];           // output_weights * output_scale (pre-folded)
};
__device__   Params g_stage;
__constant__ Params c_p;

// ---------------------------------------------------------------------------
// Prep: top-2 of gate_weights[i, 0 : 66+i]. Softmax is monotonic, so top-2 of
// probs == top-2 of raw logits. 16 threads per gate, shfl top-2 merge
// reduction; lexicographic (value, -index) compare reproduces top_k
// lower-index-wins tie-breaking. Also folds output_scale into the weights.
// ---------------------------------------------------------------------------
__global__ void __launch_bounds__(1024)
prep_kernel(const float* __restrict__ gw,
            const float* __restrict__ ow,
            const float* __restrict__ sc) {
    const int tid  = threadIdx.x;
    const int gate = tid >> 4;        // 64 gates
    const int lane = tid & 15;        // 16 threads per gate
    const float* row = gw + gate * MAXCONN;
    const int n = BASEN + gate;

    float v1 = -3.4e38f, v2 = -3.4e38f;
    int   i1 = 0x7fffffff, i2 = 0x7fffffff;
#pragma unroll
    for (int k = 0; k < (MAXCONN + 15) / 16; ++k) {
        int j = lane + k * 16;
        if (j < n) {
            float v = row[j];
            if (v > v1 || (v == v1 && j < i1)) { v2 = v1; i2 = i1; v1 = v; i1 = j; }
            else if (v > v2 || (v == v2 && j < i2)) { v2 = v; i2 = j; }
        }
    }
    // Merge across the 16-thread segment (segments are warp-aligned).
#pragma unroll
    for (int d = 8; d >= 1; d >>= 1) {
        float ov1 = __shfl_down_sync(0xffffffffu, v1, d);
        int   oi1 = __shfl_down_sync(0xffffffffu, i1, d);
        float ov2 = __shfl_down_sync(0xffffffffu, v2, d);
        int   oi2 = __shfl_down_sync(0xffffffffu, i2, d);
        // insert (ov1,oi1)
        if (ov1 > v1 || (ov1 == v1 && oi1 < i1)) { v2 = v1; i2 = i1; v1 = ov1; i1 = oi1; }
        else if (ov1 > v2 || (ov1 == v2 && oi1 < i2)) { v2 = ov1; i2 = oi1; }
        // insert (ov2,oi2)
        if (ov2 > v1 || (ov2 == v1 && oi2 < i1)) { v2 = v1; i2 = i1; v1 = ov2; i1 = oi2; }
        else if (ov2 > v2 || (ov2 == v2 && oi2 < i2)) { v2 = ov2; i2 = oi2; }
    }
    if (lane == 0)
        g_stage.off[gate] = make_uint2((unsigned)(i1 * STRIDE * 4),
                                       (unsigned)(i2 * STRIDE * 4));
    // Fold output_scale into output_weights (threads 0..511, independent work).
    if (tid < NGATES * NOUT) {
        int i = tid >> 3, j = tid & 7;
        g_stage.w[i][j] = ow[i * NOUT + j] * sc[j];
    }
}

// ---------------------------------------------------------------------------
// Main: one thread = one sample; per-sample buffer in smem [entry][sample].
// Gate loop software-pipelined depth 2: operands for gate i+2 are loaded
// BEFORE gate i's STS; stale prefetches (offset == slot(i) / slot(i+1), both
// compile-time constants after unroll) are fixed up with predicated moves.
// __launch_bounds__(128, 3): occupancy is smem-capped at 3 blocks/SM, so give
// ptxas the full ~168-register budget to actually hoist and overlap the
// pipeline instead of serializing at 32 regs.
// ---------------------------------------------------------------------------
__global__ void __launch_bounds__(BLK, 3)
circuit_kernel(const float* __restrict__ X, float* __restrict__ out) {
    extern __shared__ float sbuf[];
    const int tid = threadIdx.x;
    const long long base = (long long)blockIdx.x * BLK;

    // Load X tile transposed into smem via float4 streaming loads.
    // Element e = 4*(k*BLK+tid): sample s = e>>6, feature f = e&63;
    // bank (f*129+s)%32 = (f+s)%32 -> conflict-free STS.
    const float4* Xb = (const float4*)(X + base * NFEAT);
#pragma unroll
    for (int k = 0; k < NFEAT / 4; ++k) {
        float4 v = __ldcs(&Xb[k * BLK + tid]);
        int e = 4 * (k * BLK + tid);
        int s = e >> 6;
        int f = e & 63;
        sbuf[(f + 0) * STRIDE + s] = v.x;
        sbuf[(f + 1) * STRIDE + s] = v.y;
        sbuf[(f + 2) * STRIDE + s] = v.z;
        sbuf[(f + 3) * STRIDE + s] = v.w;
    }
    sbuf[64 * STRIDE + tid] = 0.0f;   // const 0
    sbuf[65 * STRIDE + tid] = 1.0f;   // const 1
    __syncthreads();

    char* col = (char*)(sbuf + tid);  // this sample's column (byte base)
    float acc[NOUT];
#pragma unroll
    for (int j = 0; j < NOUT; ++j) acc[j] = 0.0f;

    float A[NGATES], B[NGATES];       // short live ranges -> renamed registers
    {
        uint2 o0 = c_p.off[0], o1 = c_p.off[1];
        A[0] = *(const float*)(col + o0.x);
        B[0] = *(const float*)(col + o0.y);
        A[1] = *(const float*)(col + o1.x);
        B[1] = *(const float*)(col + o1.y);
    }

#pragma unroll
    for (int i = 0; i < NGATES; ++i) {
        float g = fmaf(-A[i], B[i], 1.0f);           // g = 1 - a*b

        uint2 onx;                                    // prefetch i+2 (pre-STS)
        if (i + 2 < NGATES) {
            onx = c_p.off[i + 2];
            A[i + 2] = *(const float*)(col + onx.x);
            B[i + 2] = *(const float*)(col + onx.y);
        }

        const unsigned Si = (unsigned)((BASEN + i) * STRIDE * 4);
        *(float*)(col + Si) = g;                      // STS, immediate offset

#pragma unroll
        for (int j = 0; j < NOUT; ++j)
            acc[j] = fmaf(g, c_p.w[i][j], acc[j]);

        // Fixups: pending prefetched operands stale w.r.t. slot(i).
        if (i + 1 < NGATES) {
            uint2 o1 = c_p.off[i + 1];
            if (o1.x == Si) A[i + 1] = g;
            if (o1.y == Si) B[i + 1] = g;
        }
        if (i + 2 < NGATES) {
            if (onx.x == Si) A[i + 2] = g;
            if (onx.y == Si) B[i + 2] = g;
        }
    }

    float4 r0 = make_float4(acc[0], acc[1], acc[2], acc[3]);
    float4 r1 = make_float4(acc[4], acc[5], acc[6], acc[7]);
    float4* op = (float4*)(out + (base + tid) * NOUT);
    __stcs(&op[0], r0);                               // streaming STG.128
    __stcs(&op[1], r1);
}

// ---------------------------------------------------------------------------
// Launch: prep -> ONE memcpy into the constant bank -> main kernel (3 nodes).
// ---------------------------------------------------------------------------
extern "C" void kernel_launch(void* const* d_in, const int* in_sizes, int n_in,
                              void* d_out, int out_size) {
    const float* X  = (const float*)d_in[0];  // (524288, 64)
    const float* gw = (const float*)d_in[1];  // (64, 130)
    const float* ow = (const float*)d_in[2];  // (64, 8)
    const float* sc = (const float*)d_in[3];  // (8,)
    float* out = (float*)d_out;               // (524288, 8)

    cudaFuncSetAttribute((const void*)circuit_kernel,
                         cudaFuncAttributeMaxDynamicSharedMemorySize, SMEM_BYTES);

    prep_kernel<<<1, 1024>>>(gw, ow, sc);

    void* gp = nullptr;
    cudaGetSymbolAddress(&gp, g_stage);
    cudaMemcpyToSymbolAsync(c_p, gp, sizeof(Params), 0,
                            cudaMemcpyDeviceToDevice, 0);

    circuit_kernel<<<NSAMPLES / BLK, BLK, SMEM_BYTES>>>(X, out);
}